// round 1
// baseline (speedup 1.0000x reference)
#include <cuda_runtime.h>
#include <math.h>

// ContrastiveLossSimCLR: N=8192, D=128, TEMP=0.5
//   zp = normalize(pred), zq = normalize(positive)
//   neg_i = sum_m exp(2*zp_i.zp_m) - exp(2) + sum_m exp(2*zp_i.zq_m)
//   loss  = mean_i( log(neg_i) - 2*zp_i.zq_i )

#define NROWS 8192
#define DDIM  128
#define EPSN  1e-8f

#define BM 64
#define BN 64
#define CSPLIT 8          // column chunks -> grid 128 x 8 = 1024 CTAs
#define SMEM_MAIN ((DDIM*BM + DDIM*BN) * sizeof(float))   // 64 KB

__device__ float g_zp[NROWS * DDIM];
__device__ float g_zq[NROWS * DDIM];
__device__ float g_sii[NROWS];
__device__ float g_part[CSPLIT * NROWS];

// ---------------------------------------------------------------------------
// Kernel 1: row L2-normalize both inputs + diagonal dot zp_i.zq_i
// one block per row, 128 threads
// ---------------------------------------------------------------------------
__global__ void normalize_kernel(const float* __restrict__ pred,
                                 const float* __restrict__ posv) {
    int row = blockIdx.x;
    int t   = threadIdx.x;           // 0..127
    float vp = pred[row * DDIM + t];
    float vq = posv[row * DDIM + t];

    float sp = vp * vp;
    float sq = vq * vq;
    #pragma unroll
    for (int o = 16; o > 0; o >>= 1) {
        sp += __shfl_xor_sync(0xffffffffu, sp, o);
        sq += __shfl_xor_sync(0xffffffffu, sq, o);
    }
    __shared__ float shp[4], shq[4], shd[4];
    int w = t >> 5, l = t & 31;
    if (l == 0) { shp[w] = sp; shq[w] = sq; }
    __syncthreads();
    sp = shp[0] + shp[1] + shp[2] + shp[3];
    sq = shq[0] + shq[1] + shq[2] + shq[3];

    float rp = 1.0f / fmaxf(sqrtf(sp), EPSN);
    float rq = 1.0f / fmaxf(sqrtf(sq), EPSN);
    float zp = vp * rp;
    float zq = vq * rq;
    g_zp[row * DDIM + t] = zp;
    g_zq[row * DDIM + t] = zq;

    float d = zp * zq;
    #pragma unroll
    for (int o = 16; o > 0; o >>= 1)
        d += __shfl_xor_sync(0xffffffffu, d, o);
    if (l == 0) shd[w] = d;
    __syncthreads();
    if (t == 0) g_sii[row] = shd[0] + shd[1] + shd[2] + shd[3];
}

// ---------------------------------------------------------------------------
// Kernel 2: fused similarity-GEMM + exp + row-sum.
// Block = 64 anchor rows x 1024-column chunk. 256 threads (16x16), 4x4 tile.
// SMEM tiles stored k-major (As[k][row]) so fragment loads are LDS.128
// conflict-free (a: 2 distinct broadcast addrs, b: 256B / 2-phase).
// ---------------------------------------------------------------------------
__global__ __launch_bounds__(256) void simclr_main_kernel() {
    extern __shared__ float smem[];
    float* As  = smem;                 // [DDIM][BM]
    float* Bs  = smem + DDIM * BM;     // [DDIM][BN]
    float* red = Bs;                   // reused for final reduction [BM][17]

    int tid = threadIdx.x;
    int tx  = tid & 15;                // column group 0..15
    int ty  = tid >> 4;                // row group 0..15
    int rowBase = blockIdx.x * BM;
    int colBase = blockIdx.y * (NROWS / CSPLIT);

    // ---- Load A tile (this block's 64 zp rows), transposed into As[k][r] ----
    {
        int r  = tid & 63;
        int f4 = tid >> 6;             // 0..3
        #pragma unroll
        for (int p = 0; p < 8; p++) {
            int c4 = f4 + p * 4;       // float4 column 0..31
            float4 v = *reinterpret_cast<const float4*>(
                &g_zp[(rowBase + r) * DDIM + c4 * 4]);
            As[(c4 * 4 + 0) * BM + r] = v.x;
            As[(c4 * 4 + 1) * BM + r] = v.y;
            As[(c4 * 4 + 2) * BM + r] = v.z;
            As[(c4 * 4 + 3) * BM + r] = v.w;
        }
    }

    float rs0 = 0.f, rs1 = 0.f, rs2 = 0.f, rs3 = 0.f;

    const int HALF  = (NROWS / CSPLIT) / BN;   // 16 tiles per matrix
    const int TILES = 2 * HALF;                // 32 total (pp then pq)

    for (int t = 0; t < TILES; t++) {
        const float* src = (t < HALF) ? g_zp : g_zq;
        int c0 = colBase + ((t < HALF) ? t : (t - HALF)) * BN;

        __syncthreads();   // previous iter done reading Bs (also covers As stores at t=0)
        {
            int r  = tid & 63;
            int f4 = tid >> 6;
            #pragma unroll
            for (int p = 0; p < 8; p++) {
                int c4 = f4 + p * 4;
                float4 v = *reinterpret_cast<const float4*>(
                    &src[(c0 + r) * DDIM + c4 * 4]);
                Bs[(c4 * 4 + 0) * BN + r] = v.x;
                Bs[(c4 * 4 + 1) * BN + r] = v.y;
                Bs[(c4 * 4 + 2) * BN + r] = v.z;
                Bs[(c4 * 4 + 3) * BN + r] = v.w;
            }
        }
        __syncthreads();

        float acc[4][4];
        #pragma unroll
        for (int i = 0; i < 4; i++)
            #pragma unroll
            for (int j = 0; j < 4; j++)
                acc[i][j] = 0.f;

        #pragma unroll 8
        for (int k = 0; k < DDIM; k++) {
            float4 a = *reinterpret_cast<const float4*>(&As[k * BM + ty * 4]);
            float4 b = *reinterpret_cast<const float4*>(&Bs[k * BN + tx * 4]);
            acc[0][0] = fmaf(a.x, b.x, acc[0][0]);
            acc[0][1] = fmaf(a.x, b.y, acc[0][1]);
            acc[0][2] = fmaf(a.x, b.z, acc[0][2]);
            acc[0][3] = fmaf(a.x, b.w, acc[0][3]);
            acc[1][0] = fmaf(a.y, b.x, acc[1][0]);
            acc[1][1] = fmaf(a.y, b.y, acc[1][1]);
            acc[1][2] = fmaf(a.y, b.z, acc[1][2]);
            acc[1][3] = fmaf(a.y, b.w, acc[1][3]);
            acc[2][0] = fmaf(a.z, b.x, acc[2][0]);
            acc[2][1] = fmaf(a.z, b.y, acc[2][1]);
            acc[2][2] = fmaf(a.z, b.z, acc[2][2]);
            acc[2][3] = fmaf(a.z, b.w, acc[2][3]);
            acc[3][0] = fmaf(a.w, b.x, acc[3][0]);
            acc[3][1] = fmaf(a.w, b.y, acc[3][1]);
            acc[3][2] = fmaf(a.w, b.z, acc[3][2]);
            acc[3][3] = fmaf(a.w, b.w, acc[3][3]);
        }

        // fused epilogue: exp(2s) and row-sum accumulation (MUFU, ~3% of FMA time)
        rs0 += __expf(2.f * acc[0][0]) + __expf(2.f * acc[0][1])
             + __expf(2.f * acc[0][2]) + __expf(2.f * acc[0][3]);
        rs1 += __expf(2.f * acc[1][0]) + __expf(2.f * acc[1][1])
             + __expf(2.f * acc[1][2]) + __expf(2.f * acc[1][3]);
        rs2 += __expf(2.f * acc[2][0]) + __expf(2.f * acc[2][1])
             + __expf(2.f * acc[2][2]) + __expf(2.f * acc[2][3]);
        rs3 += __expf(2.f * acc[3][0]) + __expf(2.f * acc[3][1])
             + __expf(2.f * acc[3][2]) + __expf(2.f * acc[3][3]);
    }

    // ---- reduce across the 16 column-group threads per row ----
    __syncthreads();
    red[(ty * 4 + 0) * 17 + tx] = rs0;
    red[(ty * 4 + 1) * 17 + tx] = rs1;
    red[(ty * 4 + 2) * 17 + tx] = rs2;
    red[(ty * 4 + 3) * 17 + tx] = rs3;
    __syncthreads();
    if (tid < BM) {
        float s = 0.f;
        #pragma unroll
        for (int x = 0; x < 16; x++) s += red[tid * 17 + x];
        // each (row-block, chunk) slot written exactly once -> deterministic,
        // no init, no atomics
        g_part[blockIdx.y * NROWS + rowBase + tid] = s;
    }
}

// ---------------------------------------------------------------------------
// Kernel 3: finalize. neg_i = sum(parts) - exp(2); loss = mean(log(neg)-2*sii)
// ---------------------------------------------------------------------------
__global__ void finalize_kernel(float* __restrict__ out) {
    __shared__ float sh[256];
    int tid = threadIdx.x;
    float local = 0.f;
    const float diag_pp = expf(2.0f);
    for (int i = tid; i < NROWS; i += 256) {
        float neg = -diag_pp;
        #pragma unroll
        for (int c = 0; c < CSPLIT; c++) neg += g_part[c * NROWS + i];
        local += logf(neg) - 2.0f * g_sii[i];
    }
    sh[tid] = local;
    __syncthreads();
    #pragma unroll
    for (int s = 128; s > 0; s >>= 1) {
        if (tid < s) sh[tid] += sh[tid + s];
        __syncthreads();
    }
    if (tid == 0) out[0] = sh[0] / (float)NROWS;
}

// ---------------------------------------------------------------------------
extern "C" void kernel_launch(void* const* d_in, const int* in_sizes, int n_in,
                              void* d_out, int out_size) {
    const float* pred     = (const float*)d_in[0];
    const float* positive = (const float*)d_in[1];
    float* out = (float*)d_out;

    cudaFuncSetAttribute(simclr_main_kernel,
                         cudaFuncAttributeMaxDynamicSharedMemorySize,
                         (int)SMEM_MAIN);

    normalize_kernel<<<NROWS, 128>>>(pred, positive);

    dim3 grid(NROWS / BM, CSPLIT);
    simclr_main_kernel<<<grid, 256, SMEM_MAIN>>>();

    finalize_kernel<<<1, 256>>>(out);
}

// round 6
// speedup vs baseline: 7.8751x; 7.8751x over previous
#include <cuda_runtime.h>
#include <cuda_bf16.h>
#include <math.h>
#include <cstdint>

// ContrastiveLossSimCLR via mma.sync bf16 HMMA (compute_103 baseline PTX;
// tcgen05 unavailable: harness compiles virtual arch without 'a' suffix).
//   zp = normalize(pred), zq = normalize(positive)   [fp32 math, stored bf16]
//   neg_i = sum_m exp(2*zp_i.zp_m) - exp(2) + sum_m exp(2*zp_i.zq_m)
//   loss  = mean_i( log(neg_i) - 2*zp_i.zq_i )        (s_ii kept exact fp32)

#define NROWS 8192
#define DDIM  128
#define EPSN  1e-8f

#define BM 128
#define BN 128
#define CSPLIT 16
#define CHUNK_COLS (NROWS / CSPLIT)            // 512 per matrix
#define TPS (CHUNK_COLS / BN)                  // 4 tiles per side
#define NT  (2 * TPS)                          // 8 tiles total

// SMEM: A (128x128 bf16 swizzled) + 2 x B buffers
#define TILE_BYTES (BM * 256)                  // 32768
#define SMEM_TOTAL (3 * TILE_BYTES)            // 98304

__device__ __nv_bfloat16 g_zp16[NROWS * DDIM];
__device__ __nv_bfloat16 g_zq16[NROWS * DDIM];
__device__ float g_sii[NROWS];
__device__ float g_part[CSPLIT * NROWS];

// ---------------------------------------------------------------------------
__device__ __forceinline__ uint32_t smem_u32(const void* p) {
    uint32_t a;
    asm("{ .reg .u64 t; cvta.to.shared.u64 t, %1; cvt.u32.u64 %0, t; }" : "=r"(a) : "l"(p));
    return a;
}
#define CP_COMMIT() asm volatile("cp.async.commit_group;" ::: "memory")
#define CP_WAIT0()  asm volatile("cp.async.wait_group 0;" ::: "memory")
#define CP_WAIT1()  asm volatile("cp.async.wait_group 1;" ::: "memory")

__device__ __forceinline__ float exp2x(float x) {   // exp(2x) = 2^(x * 2/ln2)
    float e;
    asm("ex2.approx.ftz.f32 %0, %1;" : "=f"(e) : "f"(x * 2.8853900817779268f));
    return e;
}

// cp.async a [128 rows x 128 k] bf16 tile into swizzled SMEM.
// Row = 256B = 16 chunks of 16B; chunk c stored at (c ^ (row & 7)).
__device__ __forceinline__ void cp_tile(uint32_t sbase, const __nv_bfloat16* g,
                                        int row0, int tid) {
    #pragma unroll
    for (int i = 0; i < 8; i++) {
        int idx = i * 256 + tid;
        int r = idx >> 4;                 // 0..127
        int c = idx & 15;                 // 16B chunk
        uint32_t dst = sbase + (uint32_t)(r * 256 + ((c ^ (r & 7)) << 4));
        const void* src = g + (row0 + r) * DDIM + c * 8;
        asm volatile("cp.async.cg.shared.global [%0], [%1], 16;" :: "r"(dst), "l"(src));
    }
}

// ldmatrix x4: A fragment (m16 x k16) for rows r0..r0+15, k-step ks
__device__ __forceinline__ void lda_frag(uint32_t* a, uint32_t sbase, int r0,
                                         int ks, int lane) {
    int r = r0 + (lane & 15);
    int c = (2 * ks + (lane >> 4)) ^ (r & 7);
    uint32_t addr = sbase + (uint32_t)(r * 256 + c * 16);
    asm volatile("ldmatrix.sync.aligned.m8n8.x4.shared.b16 {%0,%1,%2,%3}, [%4];"
                 : "=r"(a[0]), "=r"(a[1]), "=r"(a[2]), "=r"(a[3]) : "r"(addr));
}

// ldmatrix x4: B fragments for TWO n-tiles (16 n-rows) at k-step ks.
// regs: b[0],b[1] = n-tile0 frag; b[2],b[3] = n-tile1 frag.
__device__ __forceinline__ void ldb_frag(uint32_t* b, uint32_t sbase, int n0,
                                         int ks, int lane) {
    int g = lane >> 3;                    // 0..3
    int n = n0 + ((g >> 1) << 3) + (lane & 7);
    int c = (2 * ks + (g & 1)) ^ (n & 7);
    uint32_t addr = sbase + (uint32_t)(n * 256 + c * 16);
    asm volatile("ldmatrix.sync.aligned.m8n8.x4.shared.b16 {%0,%1,%2,%3}, [%4];"
                 : "=r"(b[0]), "=r"(b[1]), "=r"(b[2]), "=r"(b[3]) : "r"(addr));
}

__device__ __forceinline__ void mma16816(float* c, const uint32_t* a,
                                         const uint32_t* b) {
    asm volatile(
        "mma.sync.aligned.m16n8k16.row.col.f32.bf16.bf16.f32 "
        "{%0,%1,%2,%3}, {%4,%5,%6,%7}, {%8,%9}, {%0,%1,%2,%3};"
        : "+f"(c[0]), "+f"(c[1]), "+f"(c[2]), "+f"(c[3])
        : "r"(a[0]), "r"(a[1]), "r"(a[2]), "r"(a[3]), "r"(b[0]), "r"(b[1]));
}

// ---------------------------------------------------------------------------
// Kernel 1: fp32 normalize -> bf16, plus exact fp32 diagonal zp_i.zq_i
// ---------------------------------------------------------------------------
__global__ void normalize_kernel(const float* __restrict__ pred,
                                 const float* __restrict__ posv) {
    int row = blockIdx.x;
    int t   = threadIdx.x;           // 0..127
    float vp = pred[row * DDIM + t];
    float vq = posv[row * DDIM + t];

    float sp = vp * vp, sq = vq * vq;
    #pragma unroll
    for (int o = 16; o > 0; o >>= 1) {
        sp += __shfl_xor_sync(0xffffffffu, sp, o);
        sq += __shfl_xor_sync(0xffffffffu, sq, o);
    }
    __shared__ float shp[4], shq[4], shd[4];
    int w = t >> 5, l = t & 31;
    if (l == 0) { shp[w] = sp; shq[w] = sq; }
    __syncthreads();
    sp = shp[0] + shp[1] + shp[2] + shp[3];
    sq = shq[0] + shq[1] + shq[2] + shq[3];

    float zp = vp * (1.0f / fmaxf(sqrtf(sp), EPSN));
    float zq = vq * (1.0f / fmaxf(sqrtf(sq), EPSN));
    g_zp16[row * DDIM + t] = __float2bfloat16(zp);
    g_zq16[row * DDIM + t] = __float2bfloat16(zq);

    float d = zp * zq;
    #pragma unroll
    for (int o = 16; o > 0; o >>= 1)
        d += __shfl_xor_sync(0xffffffffu, d, o);
    if (l == 0) shd[w] = d;
    __syncthreads();
    if (t == 0) g_sii[row] = shd[0] + shd[1] + shd[2] + shd[3];
}

// ---------------------------------------------------------------------------
// Kernel 2: bf16 HMMA similarity GEMM + fused exp/row-sum epilogue.
// CTA: 128 anchor rows x 512-col chunk of zp then zq (8 tiles of 128).
// 8 warps: warp (wm in 0..1, wn in 0..3) owns a 64x32 subtile (4x4 mma frags).
// ---------------------------------------------------------------------------
__global__ __launch_bounds__(256, 1) void simclr_mma_kernel() {
    extern __shared__ char smem[];
    uint32_t sA = smem_u32(smem);
    uint32_t sB[2] = { sA + TILE_BYTES, sA + 2 * TILE_BYTES };

    int tid  = threadIdx.x;
    int wid  = tid >> 5, lane = tid & 31;
    int wm   = wid & 1;                  // 0..1 -> M offset wm*64
    int wn   = wid >> 1;                 // 0..3 -> N offset wn*32
    int rowBase = blockIdx.x * BM;
    int colBase = blockIdx.y * CHUNK_COLS;

    // prologue: A + B tile 0 as one cp.async group
    cp_tile(sA, g_zp16, rowBase, tid);
    cp_tile(sB[0], g_zp16, colBase, tid);
    CP_COMMIT();

    float acc[4][4][4];
    float rsum[4][2];
    #pragma unroll
    for (int mi = 0; mi < 4; mi++) { rsum[mi][0] = 0.f; rsum[mi][1] = 0.f; }

    for (int j = 0; j < NT; j++) {
        int s = j & 1;
        __syncthreads();     // all warps done reading B[s^1] (tile j-1)
        if (j + 1 < NT) {
            int t = j + 1;
            const __nv_bfloat16* src = (t < TPS) ? g_zp16 : g_zq16;
            cp_tile(sB[s ^ 1], src, colBase + (t & (TPS - 1)) * BN, tid);
            CP_COMMIT();
            CP_WAIT1();      // tile j resident (its group committed earlier)
        } else {
            CP_WAIT0();
        }
        __syncthreads();     // tile j visible to all threads

        #pragma unroll
        for (int mi = 0; mi < 4; mi++)
            #pragma unroll
            for (int ni = 0; ni < 4; ni++)
                #pragma unroll
                for (int e = 0; e < 4; e++)
                    acc[mi][ni][e] = 0.f;

        #pragma unroll
        for (int ks = 0; ks < 8; ks++) {
            uint32_t a[4][4], b[2][4];
            #pragma unroll
            for (int mi = 0; mi < 4; mi++)
                lda_frag(a[mi], sA, wm * 64 + mi * 16, ks, lane);
            ldb_frag(b[0], sB[s], wn * 32 + 0,  ks, lane);
            ldb_frag(b[1], sB[s], wn * 32 + 16, ks, lane);
            #pragma unroll
            for (int mi = 0; mi < 4; mi++) {
                mma16816(acc[mi][0], a[mi], &b[0][0]);
                mma16816(acc[mi][1], a[mi], &b[0][2]);
                mma16816(acc[mi][2], a[mi], &b[1][0]);
                mma16816(acc[mi][3], a[mi], &b[1][2]);
            }
        }

        // fused epilogue: exp(2*s), sum across this warp's 32 columns.
        // accum lane map: c0,c1 -> row (lane>>2), cols 2*(lane&3),+1 ; c2,c3 -> row+8
        #pragma unroll
        for (int mi = 0; mi < 4; mi++) {
            float s0 = 0.f, s1 = 0.f;
            #pragma unroll
            for (int ni = 0; ni < 4; ni++) {
                s0 += exp2x(acc[mi][ni][0]) + exp2x(acc[mi][ni][1]);
                s1 += exp2x(acc[mi][ni][2]) + exp2x(acc[mi][ni][3]);
            }
            s0 += __shfl_xor_sync(0xffffffffu, s0, 1);
            s0 += __shfl_xor_sync(0xffffffffu, s0, 2);
            s1 += __shfl_xor_sync(0xffffffffu, s1, 1);
            s1 += __shfl_xor_sync(0xffffffffu, s1, 2);
            rsum[mi][0] += s0;
            rsum[mi][1] += s1;
        }
    }

    // cross-warp (wn) reduction through SMEM, then one deterministic write/row
    __syncthreads();
    float* red = (float*)smem;           // [128 rows][4 wn]
    if ((lane & 3) == 0) {
        #pragma unroll
        for (int mi = 0; mi < 4; mi++) {
            int r0 = wm * 64 + mi * 16 + (lane >> 2);
            red[r0 * 4 + wn]       = rsum[mi][0];
            red[(r0 + 8) * 4 + wn] = rsum[mi][1];
        }
    }
    __syncthreads();
    if (tid < BM) {
        float v = red[tid * 4 + 0] + red[tid * 4 + 1]
                + red[tid * 4 + 2] + red[tid * 4 + 3];
        g_part[blockIdx.y * NROWS + rowBase + tid] = v;
    }
}

// ---------------------------------------------------------------------------
// Kernel 3: finalize. neg_i = sum(parts) - exp(2); loss = mean(log(neg)-2*sii)
// ---------------------------------------------------------------------------
__global__ void finalize_kernel(float* __restrict__ out) {
    __shared__ float sh[256];
    int tid = threadIdx.x;
    float local = 0.f;
    const float diag_pp = expf(2.0f);
    for (int i = tid; i < NROWS; i += 256) {
        float neg = -diag_pp;
        #pragma unroll
        for (int c = 0; c < CSPLIT; c++) neg += g_part[c * NROWS + i];
        local += logf(neg) - 2.0f * g_sii[i];
    }
    sh[tid] = local;
    __syncthreads();
    #pragma unroll
    for (int s = 128; s > 0; s >>= 1) {
        if (tid < s) sh[tid] += sh[tid + s];
        __syncthreads();
    }
    if (tid == 0) out[0] = sh[0] / (float)NROWS;
}

// ---------------------------------------------------------------------------
extern "C" void kernel_launch(void* const* d_in, const int* in_sizes, int n_in,
                              void* d_out, int out_size) {
    const float* pred     = (const float*)d_in[0];
    const float* positive = (const float*)d_in[1];
    float* out = (float*)d_out;

    cudaFuncSetAttribute(simclr_mma_kernel,
                         cudaFuncAttributeMaxDynamicSharedMemorySize, SMEM_TOTAL);

    normalize_kernel<<<NROWS, 128>>>(pred, positive);

    dim3 grid(NROWS / BM, CSPLIT);
    simclr_mma_kernel<<<grid, 256, SMEM_TOTAL>>>();

    finalize_kernel<<<1, 256>>>(out);
}

// round 7
// speedup vs baseline: 10.9054x; 1.3848x over previous
#include <cuda_runtime.h>
#include <cuda_bf16.h>
#include <math.h>
#include <cstdint>

// ContrastiveLossSimCLR via mma.sync bf16 HMMA (compute_103 baseline PTX).
//   zp = normalize(pred), zq = normalize(positive)   [fp32 math, stored bf16]
//   neg_i = sum_m exp(2*zp_i.zp_m) - exp(2) + sum_m exp(2*zp_i.zq_m)
//   loss  = mean_i( log(neg_i) - 2*zp_i.zq_i )        (s_ii kept exact fp32)

#define NROWS 8192
#define DDIM  128
#define EPSN  1e-8f

#define BM 128
#define BN 128
#define CSPLIT 16
#define CHUNK_COLS (NROWS / CSPLIT)            // 512 per matrix
#define TPS (CHUNK_COLS / BN)                  // 4 tiles per side
#define NT  (2 * TPS)                          // 8 tiles total

// SMEM: A (128x128 bf16 swizzled) + 2 x B buffers; 96KB -> 2 CTAs/SM
#define TILE_BYTES (BM * 256)                  // 32768
#define SMEM_TOTAL (3 * TILE_BYTES)            // 98304

#define FBLOCKS 32                              // finalize stage-1 blocks

__device__ __nv_bfloat16 g_zp16[NROWS * DDIM];
__device__ __nv_bfloat16 g_zq16[NROWS * DDIM];
__device__ float g_sii[NROWS];
__device__ float g_part[CSPLIT * NROWS];
__device__ float g_lpart[FBLOCKS];

// ---------------------------------------------------------------------------
__device__ __forceinline__ uint32_t smem_u32(const void* p) {
    uint32_t a;
    asm("{ .reg .u64 t; cvta.to.shared.u64 t, %1; cvt.u32.u64 %0, t; }" : "=r"(a) : "l"(p));
    return a;
}
#define CP_COMMIT() asm volatile("cp.async.commit_group;" ::: "memory")
#define CP_WAIT0()  asm volatile("cp.async.wait_group 0;" ::: "memory")
#define CP_WAIT1()  asm volatile("cp.async.wait_group 1;" ::: "memory")

__device__ __forceinline__ float exp2x(float x) {   // exp(2x) = 2^(x * 2/ln2)
    float e;
    asm("ex2.approx.ftz.f32 %0, %1;" : "=f"(e) : "f"(x * 2.8853900817779268f));
    return e;
}

// cp.async a [128 rows x 128 k] bf16 tile into swizzled SMEM.
// Row = 256B = 16 chunks of 16B; chunk c stored at (c ^ (row & 7)).
__device__ __forceinline__ void cp_tile(uint32_t sbase, const __nv_bfloat16* g,
                                        int row0, int tid) {
    #pragma unroll
    for (int i = 0; i < 8; i++) {
        int idx = i * 256 + tid;
        int r = idx >> 4;                 // 0..127
        int c = idx & 15;                 // 16B chunk
        uint32_t dst = sbase + (uint32_t)(r * 256 + ((c ^ (r & 7)) << 4));
        const void* src = g + (row0 + r) * DDIM + c * 8;
        asm volatile("cp.async.cg.shared.global [%0], [%1], 16;" :: "r"(dst), "l"(src));
    }
}

// ldmatrix x4: A fragment (m16 x k16) for rows r0..r0+15, k-step ks
__device__ __forceinline__ void lda_frag(uint32_t* a, uint32_t sbase, int r0,
                                         int ks, int lane) {
    int r = r0 + (lane & 15);
    int c = (2 * ks + (lane >> 4)) ^ (r & 7);
    uint32_t addr = sbase + (uint32_t)(r * 256 + c * 16);
    asm volatile("ldmatrix.sync.aligned.m8n8.x4.shared.b16 {%0,%1,%2,%3}, [%4];"
                 : "=r"(a[0]), "=r"(a[1]), "=r"(a[2]), "=r"(a[3]) : "r"(addr));
}

// ldmatrix x4: B fragments for TWO n-tiles (16 n-rows) at k-step ks.
__device__ __forceinline__ void ldb_frag(uint32_t* b, uint32_t sbase, int n0,
                                         int ks, int lane) {
    int g = lane >> 3;                    // 0..3
    int n = n0 + ((g >> 1) << 3) + (lane & 7);
    int c = (2 * ks + (g & 1)) ^ (n & 7);
    uint32_t addr = sbase + (uint32_t)(n * 256 + c * 16);
    asm volatile("ldmatrix.sync.aligned.m8n8.x4.shared.b16 {%0,%1,%2,%3}, [%4];"
                 : "=r"(b[0]), "=r"(b[1]), "=r"(b[2]), "=r"(b[3]) : "r"(addr));
}

__device__ __forceinline__ void mma16816(float* c, const uint32_t* a,
                                         const uint32_t* b) {
    asm volatile(
        "mma.sync.aligned.m16n8k16.row.col.f32.bf16.bf16.f32 "
        "{%0,%1,%2,%3}, {%4,%5,%6,%7}, {%8,%9}, {%0,%1,%2,%3};"
        : "+f"(c[0]), "+f"(c[1]), "+f"(c[2]), "+f"(c[3])
        : "r"(a[0]), "r"(a[1]), "r"(a[2]), "r"(a[3]), "r"(b[0]), "r"(b[1]));
}

// ---------------------------------------------------------------------------
// Kernel 1: warp-per-row fp32 normalize -> bf16 + exact fp32 diagonal dot.
// 256 threads = 8 warps = 8 rows per block; float4 loads, shfl-only reduction.
// ---------------------------------------------------------------------------
__global__ __launch_bounds__(256) void normalize_kernel(
        const float* __restrict__ pred, const float* __restrict__ posv) {
    int w    = threadIdx.x >> 5;
    int lane = threadIdx.x & 31;
    int row  = blockIdx.x * 8 + w;

    float4 vp = reinterpret_cast<const float4*>(pred + row * DDIM)[lane];
    float4 vq = reinterpret_cast<const float4*>(posv + row * DDIM)[lane];

    float sp = vp.x*vp.x + vp.y*vp.y + vp.z*vp.z + vp.w*vp.w;
    float sq = vq.x*vq.x + vq.y*vq.y + vq.z*vq.z + vq.w*vq.w;
    #pragma unroll
    for (int o = 16; o > 0; o >>= 1) {
        sp += __shfl_xor_sync(0xffffffffu, sp, o);
        sq += __shfl_xor_sync(0xffffffffu, sq, o);
    }
    float rp = 1.0f / fmaxf(sqrtf(sp), EPSN);
    float rq = 1.0f / fmaxf(sqrtf(sq), EPSN);

    float4 zp = make_float4(vp.x*rp, vp.y*rp, vp.z*rp, vp.w*rp);
    float4 zq = make_float4(vq.x*rq, vq.y*rq, vq.z*rq, vq.w*rq);

    __nv_bfloat162* op = reinterpret_cast<__nv_bfloat162*>(g_zp16 + row * DDIM) + lane * 2;
    __nv_bfloat162* oq = reinterpret_cast<__nv_bfloat162*>(g_zq16 + row * DDIM) + lane * 2;
    op[0] = __floats2bfloat162_rn(zp.x, zp.y);
    op[1] = __floats2bfloat162_rn(zp.z, zp.w);
    oq[0] = __floats2bfloat162_rn(zq.x, zq.y);
    oq[1] = __floats2bfloat162_rn(zq.z, zq.w);

    float d = zp.x*zq.x + zp.y*zq.y + zp.z*zq.z + zp.w*zq.w;
    #pragma unroll
    for (int o = 16; o > 0; o >>= 1)
        d += __shfl_xor_sync(0xffffffffu, d, o);
    if (lane == 0) g_sii[row] = d;
}

// ---------------------------------------------------------------------------
// Kernel 2: bf16 HMMA similarity GEMM + fused exp/row-sum epilogue.
// CTA: 128 anchor rows x 512-col chunk of zp then zq (8 tiles of 128).
// 8 warps: warp (wm, wn) owns a 64x32 subtile (4x4 mma frags).
// 2 CTAs/SM (96KB smem, <=128 regs) so epilogue/barriers hide under HMMA.
// ---------------------------------------------------------------------------
__global__ __launch_bounds__(256, 2) void simclr_mma_kernel() {
    extern __shared__ char smem[];
    uint32_t sA = smem_u32(smem);
    uint32_t sB[2] = { sA + TILE_BYTES, sA + 2 * TILE_BYTES };

    int tid  = threadIdx.x;
    int wid  = tid >> 5, lane = tid & 31;
    int wm   = wid & 1;                  // 0..1 -> M offset wm*64
    int wn   = wid >> 1;                 // 0..3 -> N offset wn*32
    int rowBase = blockIdx.x * BM;
    int colBase = blockIdx.y * CHUNK_COLS;

    // prologue: A + B tile 0 as one cp.async group
    cp_tile(sA, g_zp16, rowBase, tid);
    cp_tile(sB[0], g_zp16, colBase, tid);
    CP_COMMIT();

    float acc[4][4][4];
    float rsum[4][2];                    // per-LANE partials; shfl-reduced once at end
    #pragma unroll
    for (int mi = 0; mi < 4; mi++) { rsum[mi][0] = 0.f; rsum[mi][1] = 0.f; }

    for (int j = 0; j < NT; j++) {
        int s = j & 1;
        __syncthreads();     // all warps done reading B[s^1] (tile j-1)
        if (j + 1 < NT) {
            int t = j + 1;
            const __nv_bfloat16* src = (t < TPS) ? g_zp16 : g_zq16;
            cp_tile(sB[s ^ 1], src, colBase + (t & (TPS - 1)) * BN, tid);
            CP_COMMIT();
            CP_WAIT1();      // tile j resident (its group committed earlier)
        } else {
            CP_WAIT0();
        }
        __syncthreads();     // tile j visible to all threads

        #pragma unroll
        for (int mi = 0; mi < 4; mi++)
            #pragma unroll
            for (int ni = 0; ni < 4; ni++)
                #pragma unroll
                for (int e = 0; e < 4; e++)
                    acc[mi][ni][e] = 0.f;

        #pragma unroll
        for (int ks = 0; ks < 8; ks++) {
            uint32_t a[4][4], b[2][4];
            #pragma unroll
            for (int mi = 0; mi < 4; mi++)
                lda_frag(a[mi], sA, wm * 64 + mi * 16, ks, lane);
            ldb_frag(b[0], sB[s], wn * 32 + 0,  ks, lane);
            ldb_frag(b[1], sB[s], wn * 32 + 16, ks, lane);
            #pragma unroll
            for (int mi = 0; mi < 4; mi++) {
                mma16816(acc[mi][0], a[mi], &b[0][0]);
                mma16816(acc[mi][1], a[mi], &b[0][2]);
                mma16816(acc[mi][2], a[mi], &b[1][0]);
                mma16816(acc[mi][3], a[mi], &b[1][2]);
            }
        }

        // fused epilogue: exp(2*s) into per-lane partial sums (no shfl here)
        #pragma unroll
        for (int mi = 0; mi < 4; mi++) {
            #pragma unroll
            for (int ni = 0; ni < 4; ni++) {
                rsum[mi][0] += exp2x(acc[mi][ni][0]) + exp2x(acc[mi][ni][1]);
                rsum[mi][1] += exp2x(acc[mi][ni][2]) + exp2x(acc[mi][ni][3]);
            }
        }
    }

    // single lane-group reduction (4 lanes share a row) after all tiles
    #pragma unroll
    for (int mi = 0; mi < 4; mi++) {
        rsum[mi][0] += __shfl_xor_sync(0xffffffffu, rsum[mi][0], 1);
        rsum[mi][0] += __shfl_xor_sync(0xffffffffu, rsum[mi][0], 2);
        rsum[mi][1] += __shfl_xor_sync(0xffffffffu, rsum[mi][1], 1);
        rsum[mi][1] += __shfl_xor_sync(0xffffffffu, rsum[mi][1], 2);
    }

    // cross-warp (wn) reduction through SMEM, then one deterministic write/row
    __syncthreads();
    float* red = (float*)smem;           // [128 rows][4 wn]
    if ((lane & 3) == 0) {
        #pragma unroll
        for (int mi = 0; mi < 4; mi++) {
            int r0 = wm * 64 + mi * 16 + (lane >> 2);
            red[r0 * 4 + wn]       = rsum[mi][0];
            red[(r0 + 8) * 4 + wn] = rsum[mi][1];
        }
    }
    __syncthreads();
    if (tid < BM) {
        float v = red[tid * 4 + 0] + red[tid * 4 + 1]
                + red[tid * 4 + 2] + red[tid * 4 + 3];
        g_part[blockIdx.y * NROWS + rowBase + tid] = v;
    }
}

// ---------------------------------------------------------------------------
// Kernel 3a: per-row loss, 32 blocks x 256 threads = one thread per row.
// ---------------------------------------------------------------------------
__global__ __launch_bounds__(256) void finalize1_kernel() {
    __shared__ float sh[256];
    int tid = threadIdx.x;
    int i   = blockIdx.x * 256 + tid;
    const float diag_pp = expf(2.0f);

    float neg = -diag_pp;
    #pragma unroll
    for (int c = 0; c < CSPLIT; c++) neg += g_part[c * NROWS + i];
    sh[tid] = logf(neg) - 2.0f * g_sii[i];
    __syncthreads();
    #pragma unroll
    for (int s = 128; s > 0; s >>= 1) {
        if (tid < s) sh[tid] += sh[tid + s];
        __syncthreads();
    }
    if (tid == 0) g_lpart[blockIdx.x] = sh[0];
}

// Kernel 3b: final 32-wide reduction + mean.
__global__ void finalize2_kernel(float* __restrict__ out) {
    int lane = threadIdx.x;
    float s = g_lpart[lane];
    #pragma unroll
    for (int o = 16; o > 0; o >>= 1)
        s += __shfl_xor_sync(0xffffffffu, s, o);
    if (lane == 0) out[0] = s / (float)NROWS;
}

// ---------------------------------------------------------------------------
extern "C" void kernel_launch(void* const* d_in, const int* in_sizes, int n_in,
                              void* d_out, int out_size) {
    const float* pred     = (const float*)d_in[0];
    const float* positive = (const float*)d_in[1];
    float* out = (float*)d_out;

    cudaFuncSetAttribute(simclr_mma_kernel,
                         cudaFuncAttributeMaxDynamicSharedMemorySize, SMEM_TOTAL);

    normalize_kernel<<<NROWS / 8, 256>>>(pred, positive);

    dim3 grid(NROWS / BM, CSPLIT);
    simclr_mma_kernel<<<grid, 256, SMEM_TOTAL>>>();

    finalize1_kernel<<<FBLOCKS, 256>>>();
    finalize2_kernel<<<1, 32>>>(out);
}

// round 14
// speedup vs baseline: 12.8503x; 1.1783x over previous
#include <cuda_runtime.h>
#include <cuda_bf16.h>
#include <math.h>
#include <cstdint>

// ContrastiveLossSimCLR via mma.sync bf16 HMMA, exploiting s_pp symmetry.
//   zp = normalize(pred), zq = normalize(positive)   [fp32 math, stored bf16]
//   neg_i = sum_m exp(2*zp_i.zp_m) - exp(2) + sum_m exp(2*zp_i.zq_m)
//   loss  = mean_i( log(neg_i) - 2*zp_i.zq_i )        (s_ii kept exact fp32)
//
// pp tiles: wrapped diagonal (I,(I+d)%64), d=0..31 all I, d=32 for I<32 (2080
// tiles instead of 4096); each off-diagonal tile also emits COLUMN sums, which
// by symmetry are the row sums of the mirror tile. pq tiles: full 4096.

#define NROWS 8192
#define DDIM  128
#define EPSN  1e-8f

#define BM 128
#define BN 128
#define NBLK (NROWS / BM)                      // 64 row/col blocks

// SMEM: A (128x128 bf16 swizzled) + 2 x B buffers; 96KB -> 2 CTAs/SM
#define TILE_BYTES (BM * 256)                  // 32768
#define SMEM_TOTAL (3 * TILE_BYTES)            // 98304

#define PQ_CTAS 512                            // 64 I-blocks x 8 col groups
#define PP_CTAS 512                            // 64 I-blocks x 8 d groups
#define FBLOCKS 32

__device__ __nv_bfloat16 g_zp16[NROWS * DDIM];
__device__ __nv_bfloat16 g_zq16[NROWS * DDIM];
__device__ float g_sii[NROWS];
__device__ float g_rpart[8 * NROWS];           // pp row partials   [g][row]
__device__ float g_qpart[8 * NROWS];           // pq row partials   [c][row]
__device__ float g_cpart[32 * 2 * NROWS];      // pp col partials [d-1][wm][col]
__device__ float g_lpart[FBLOCKS];

// ---------------------------------------------------------------------------
__device__ __forceinline__ uint32_t smem_u32(const void* p) {
    uint32_t a;
    asm("{ .reg .u64 t; cvta.to.shared.u64 t, %1; cvt.u32.u64 %0, t; }" : "=r"(a) : "l"(p));
    return a;
}
#define CP_COMMIT() asm volatile("cp.async.commit_group;" ::: "memory")
#define CP_WAIT0()  asm volatile("cp.async.wait_group 0;" ::: "memory")
#define CP_WAIT1()  asm volatile("cp.async.wait_group 1;" ::: "memory")

__device__ __forceinline__ float exp2x(float x) {   // exp(2x) = 2^(x * 2/ln2)
    float e;
    asm("ex2.approx.ftz.f32 %0, %1;" : "=f"(e) : "f"(x * 2.8853900817779268f));
    return e;
}

// cp.async a [128 rows x 128 k] bf16 tile into swizzled SMEM.
__device__ __forceinline__ void cp_tile(uint32_t sbase, const __nv_bfloat16* g,
                                        int row0, int tid) {
    #pragma unroll
    for (int i = 0; i < 8; i++) {
        int idx = i * 256 + tid;
        int r = idx >> 4;                 // 0..127
        int c = idx & 15;                 // 16B chunk
        uint32_t dst = sbase + (uint32_t)(r * 256 + ((c ^ (r & 7)) << 4));
        const void* src = g + (row0 + r) * DDIM + c * 8;
        asm volatile("cp.async.cg.shared.global [%0], [%1], 16;" :: "r"(dst), "l"(src));
    }
}

// ldmatrix x4: A fragment (m16 x k16) for rows r0..r0+15, k-step ks
__device__ __forceinline__ void lda_frag(uint32_t* a, uint32_t sbase, int r0,
                                         int ks, int lane) {
    int r = r0 + (lane & 15);
    int c = (2 * ks + (lane >> 4)) ^ (r & 7);
    uint32_t addr = sbase + (uint32_t)(r * 256 + c * 16);
    asm volatile("ldmatrix.sync.aligned.m8n8.x4.shared.b16 {%0,%1,%2,%3}, [%4];"
                 : "=r"(a[0]), "=r"(a[1]), "=r"(a[2]), "=r"(a[3]) : "r"(addr));
}

// ldmatrix x4: B fragments for TWO n-tiles (16 n-rows) at k-step ks.
__device__ __forceinline__ void ldb_frag(uint32_t* b, uint32_t sbase, int n0,
                                         int ks, int lane) {
    int g = lane >> 3;                    // 0..3
    int n = n0 + ((g >> 1) << 3) + (lane & 7);
    int c = (2 * ks + (g & 1)) ^ (n & 7);
    uint32_t addr = sbase + (uint32_t)(n * 256 + c * 16);
    asm volatile("ldmatrix.sync.aligned.m8n8.x4.shared.b16 {%0,%1,%2,%3}, [%4];"
                 : "=r"(b[0]), "=r"(b[1]), "=r"(b[2]), "=r"(b[3]) : "r"(addr));
}

__device__ __forceinline__ void mma16816(float* c, const uint32_t* a,
                                         const uint32_t* b) {
    asm volatile(
        "mma.sync.aligned.m16n8k16.row.col.f32.bf16.bf16.f32 "
        "{%0,%1,%2,%3}, {%4,%5,%6,%7}, {%8,%9}, {%0,%1,%2,%3};"
        : "+f"(c[0]), "+f"(c[1]), "+f"(c[2]), "+f"(c[3])
        : "r"(a[0]), "r"(a[1]), "r"(a[2]), "r"(a[3]), "r"(b[0]), "r"(b[1]));
}

// pp d-schedule: group g owns d = {4g..4g+3}; group 0 additionally d=32 (I<32).
__device__ __forceinline__ int pp_d(int g, int t) {
    return g ? (g * 4 + t) : (t < 4 ? t : 32);
}

// ---------------------------------------------------------------------------
// Kernel 1: warp-per-row fp32 normalize -> bf16 + exact fp32 diagonal dot.
// ---------------------------------------------------------------------------
__global__ __launch_bounds__(256) void normalize_kernel(
        const float* __restrict__ pred, const float* __restrict__ posv) {
    int w    = threadIdx.x >> 5;
    int lane = threadIdx.x & 31;
    int row  = blockIdx.x * 8 + w;

    float4 vp = reinterpret_cast<const float4*>(pred + row * DDIM)[lane];
    float4 vq = reinterpret_cast<const float4*>(posv + row * DDIM)[lane];

    float sp = vp.x*vp.x + vp.y*vp.y + vp.z*vp.z + vp.w*vp.w;
    float sq = vq.x*vq.x + vq.y*vq.y + vq.z*vq.z + vq.w*vq.w;
    #pragma unroll
    for (int o = 16; o > 0; o >>= 1) {
        sp += __shfl_xor_sync(0xffffffffu, sp, o);
        sq += __shfl_xor_sync(0xffffffffu, sq, o);
    }
    float rp = 1.0f / fmaxf(sqrtf(sp), EPSN);
    float rq = 1.0f / fmaxf(sqrtf(sq), EPSN);

    float4 zp = make_float4(vp.x*rp, vp.y*rp, vp.z*rp, vp.w*rp);
    float4 zq = make_float4(vq.x*rq, vq.y*rq, vq.z*rq, vq.w*rq);

    __nv_bfloat162* op = reinterpret_cast<__nv_bfloat162*>(g_zp16 + row * DDIM) + lane * 2;
    __nv_bfloat162* oq = reinterpret_cast<__nv_bfloat162*>(g_zq16 + row * DDIM) + lane * 2;
    op[0] = __floats2bfloat162_rn(zp.x, zp.y);
    op[1] = __floats2bfloat162_rn(zp.z, zp.w);
    oq[0] = __floats2bfloat162_rn(zq.x, zq.y);
    oq[1] = __floats2bfloat162_rn(zq.z, zq.w);

    float d = zp.x*zq.x + zp.y*zq.y + zp.z*zq.z + zp.w*zq.w;
    #pragma unroll
    for (int o = 16; o > 0; o >>= 1)
        d += __shfl_xor_sync(0xffffffffu, d, o);
    if (lane == 0) g_sii[row] = d;
}

// ---------------------------------------------------------------------------
// Kernel 2: merged pq + symmetric-pp HMMA GEMM with fused exp/row(+col) sums.
// bid < PQ_CTAS: pq role (I = bid>>3, c = bid&7): 8 zq tiles, row sums only.
// bid >= PQ_CTAS: pp role (I, g): 4-5 zp tiles (wrapped diagonal), row sums
//                 for block I + column sums for each target block (d>0).
// ---------------------------------------------------------------------------
__global__ __launch_bounds__(256, 2) void simclr_mma_kernel() {
    extern __shared__ char smem[];
    uint32_t sA = smem_u32(smem);
    uint32_t sB[2] = { sA + TILE_BYTES, sA + 2 * TILE_BYTES };

    int tid  = threadIdx.x;
    int wid  = tid >> 5, lane = tid & 31;
    int wm   = wid & 1;                  // M offset wm*64
    int wn   = wid >> 1;                 // N offset wn*32
    int bid  = blockIdx.x;

    bool isPQ = bid < PQ_CTAS;
    int I, g, nt;
    if (isPQ) { I = bid >> 3;              g = bid & 7; nt = 8; }
    else      { I = (bid - PQ_CTAS) >> 3;  g = (bid - PQ_CTAS) & 7;
                nt = (g == 0 && I < 32) ? 5 : 4; }
    int rowBase = I * BM;
    const __nv_bfloat16* src = isPQ ? g_zq16 : g_zp16;

    // B-tile first row for tile index t
    auto tile_row0 = [&](int t) -> int {
        if (isPQ) return (g * 8 + t) * BM;
        return ((I + pp_d(g, t)) & (NBLK - 1)) * BM;
    };

    // prologue: A + B tile 0 as one cp.async group
    cp_tile(sA, g_zp16, rowBase, tid);
    cp_tile(sB[0], src, tile_row0(0), tid);
    CP_COMMIT();

    float acc[4][4][4];
    float rsum[4][2];                    // per-lane row partials
    #pragma unroll
    for (int mi = 0; mi < 4; mi++) { rsum[mi][0] = 0.f; rsum[mi][1] = 0.f; }

    for (int j = 0; j < nt; j++) {
        int s = j & 1;
        __syncthreads();     // all warps done reading B[s^1]
        if (j + 1 < nt) {
            cp_tile(sB[s ^ 1], src, tile_row0(j + 1), tid);
            CP_COMMIT();
            CP_WAIT1();      // tile j resident
        } else {
            CP_WAIT0();
        }
        __syncthreads();     // tile j visible

        #pragma unroll
        for (int mi = 0; mi < 4; mi++)
            #pragma unroll
            for (int ni = 0; ni < 4; ni++)
                #pragma unroll
                for (int e = 0; e < 4; e++)
                    acc[mi][ni][e] = 0.f;

        #pragma unroll
        for (int ks = 0; ks < 8; ks++) {
            uint32_t a[4][4], b[2][4];
            #pragma unroll
            for (int mi = 0; mi < 4; mi++)
                lda_frag(a[mi], sA, wm * 64 + mi * 16, ks, lane);
            ldb_frag(b[0], sB[s], wn * 32 + 0,  ks, lane);
            ldb_frag(b[1], sB[s], wn * 32 + 16, ks, lane);
            #pragma unroll
            for (int mi = 0; mi < 4; mi++) {
                mma16816(acc[mi][0], a[mi], &b[0][0]);
                mma16816(acc[mi][1], a[mi], &b[0][2]);
                mma16816(acc[mi][2], a[mi], &b[1][0]);
                mma16816(acc[mi][3], a[mi], &b[1][2]);
            }
        }

        // epilogue: exp(2*s); row partials always, column partials for pp d>0.
        int d = isPQ ? 0 : pp_d(g, j);
        bool colout = (!isPQ) && (d > 0);

        float cp_[4][2];
        #pragma unroll
        for (int ni = 0; ni < 4; ni++) { cp_[ni][0] = 0.f; cp_[ni][1] = 0.f; }

        #pragma unroll
        for (int mi = 0; mi < 4; mi++) {
            #pragma unroll
            for (int ni = 0; ni < 4; ni++) {
                float e0 = exp2x(acc[mi][ni][0]);
                float e1 = exp2x(acc[mi][ni][1]);
                float e2 = exp2x(acc[mi][ni][2]);
                float e3 = exp2x(acc[mi][ni][3]);
                rsum[mi][0] += e0 + e1;
                rsum[mi][1] += e2 + e3;
                if (colout) {
                    cp_[ni][0] += e0 + e2;   // col C   (rows R, R+8)
                    cp_[ni][1] += e1 + e3;   // col C+1
                }
            }
        }

        if (colout) {
            // sum over the warp's 64 rows: butterfly across lane>>2 groups
            #pragma unroll
            for (int ni = 0; ni < 4; ni++)
                #pragma unroll
                for (int par = 0; par < 2; par++) {
                    float v = cp_[ni][par];
                    v += __shfl_xor_sync(0xffffffffu, v, 4);
                    v += __shfl_xor_sync(0xffffffffu, v, 8);
                    v += __shfl_xor_sync(0xffffffffu, v, 16);
                    cp_[ni][par] = v;
                }
            if (lane < 4) {
                int K = (I + d) & (NBLK - 1);
                float* dst = g_cpart + (uint32_t)((d - 1) * 2 + wm) * NROWS
                           + K * BM + wn * 32;
                #pragma unroll
                for (int ni = 0; ni < 4; ni++) {
                    dst[ni * 8 + 2 * lane + 0] = cp_[ni][0];
                    dst[ni * 8 + 2 * lane + 1] = cp_[ni][1];
                }
            }
        }
    }

    // lane-group reduction for rows (4 lanes share a row)
    #pragma unroll
    for (int mi = 0; mi < 4; mi++) {
        rsum[mi][0] += __shfl_xor_sync(0xffffffffu, rsum[mi][0], 1);
        rsum[mi][0] += __shfl_xor_sync(0xffffffffu, rsum[mi][0], 2);
        rsum[mi][1] += __shfl_xor_sync(0xffffffffu, rsum[mi][1], 1);
        rsum[mi][1] += __shfl_xor_sync(0xffffffffu, rsum[mi][1], 2);
    }

    // cross-warp (wn) reduction through SMEM, one deterministic write per row
    __syncthreads();
    float* red = (float*)smem;           // [128 rows][4 wn]
    if ((lane & 3) == 0) {
        #pragma unroll
        for (int mi = 0; mi < 4; mi++) {
            int r0 = wm * 64 + mi * 16 + (lane >> 2);
            red[r0 * 4 + wn]       = rsum[mi][0];
            red[(r0 + 8) * 4 + wn] = rsum[mi][1];
        }
    }
    __syncthreads();
    if (tid < BM) {
        float v = red[tid * 4 + 0] + red[tid * 4 + 1]
                + red[tid * 4 + 2] + red[tid * 4 + 3];
        float* outp = isPQ ? (g_qpart + (uint32_t)g * NROWS)
                           : (g_rpart + (uint32_t)g * NROWS);
        outp[rowBase + tid] = v;
    }
}

// ---------------------------------------------------------------------------
// Kernel 3a: per-row loss. Slots per row i:
//   8 qpart + 8 rpart + d=1..31 (2 wm each) + d=32 (only rows >= 4096).
// ---------------------------------------------------------------------------
__global__ __launch_bounds__(256) void finalize1_kernel() {
    __shared__ float sh[256];
    int tid = threadIdx.x;
    int i   = blockIdx.x * 256 + tid;
    const float diag_pp = expf(2.0f);

    float neg = -diag_pp;
    #pragma unroll
    for (int s = 0; s < 8; s++) neg += g_qpart[s * NROWS + i];
    #pragma unroll
    for (int s = 0; s < 8; s++) neg += g_rpart[s * NROWS + i];
    #pragma unroll
    for (int d = 1; d < 32; d++)
        neg += g_cpart[((d - 1) * 2 + 0) * NROWS + i]
             + g_cpart[((d - 1) * 2 + 1) * NROWS + i];
    if (i >= 32 * BM)   // d=32 slot only written for target blocks 32..63
        neg += g_cpart[(31 * 2 + 0) * NROWS + i]
             + g_cpart[(31 * 2 + 1) * NROWS + i];

    sh[tid] = logf(neg) - 2.0f * g_sii[i];
    __syncthreads();
    #pragma unroll
    for (int s = 128; s > 0; s >>= 1) {
        if (tid < s) sh[tid] += sh[tid + s];
        __syncthreads();
    }
    if (tid == 0) g_lpart[blockIdx.x] = sh[0];
}

// Kernel 3b: final 32-wide reduction + mean.
__global__ void finalize2_kernel(float* __restrict__ out) {
    int lane = threadIdx.x;
    float s = g_lpart[lane];
    #pragma unroll
    for (int o = 16; o > 0; o >>= 1)
        s += __shfl_xor_sync(0xffffffffu, s, o);
    if (lane == 0) out[0] = s / (float)NROWS;
}

// ---------------------------------------------------------------------------
extern "C" void kernel_launch(void* const* d_in, const int* in_sizes, int n_in,
                              void* d_out, int out_size) {
    const float* pred     = (const float*)d_in[0];
    const float* positive = (const float*)d_in[1];
    float* out = (float*)d_out;

    cudaFuncSetAttribute(simclr_mma_kernel,
                         cudaFuncAttributeMaxDynamicSharedMemorySize, SMEM_TOTAL);

    normalize_kernel<<<NROWS / 8, 256>>>(pred, positive);

    simclr_mma_kernel<<<PQ_CTAS + PP_CTAS, 256, SMEM_TOTAL>>>();

    finalize1_kernel<<<FBLOCKS, 256>>>();
    finalize2_kernel<<<1, 32>>>(out);
}